// round 2
// baseline (speedup 1.0000x reference)
#include <cuda_runtime.h>

// Problem constants
#define FEAT 2048
#define NCLS 751
#define NP   64
#define NG   256
#define EPSV 1e-5

// GEMM tiling
#define TN  128   // n-rows per block (n = i*NG + j)
#define TCc 128   // classes per block
#define TK  16    // k-slice
#define LDA 132   // padded SMEM row stride (floats), keeps 16B alignment

// Scratch (device globals: no allocation allowed in kernel_launch)
__device__ float d_scale[FEAT];        // gamma * rsqrt(var+eps)
__device__ float d_shift[FEAT];        // beta - mean*scale
__device__ float d_Wp[NCLS * FEAT];    // W' = W * scale  (folded BN)
__device__ float d_C[NCLS];            // per-class constant b + shift@W^T

// ---------------------------------------------------------------------------
// Stage A: exact batch stats from per-feature moments of probe/gallery.
// Batch = full cross product {i}x{j}, so E_{ij}[p^a g^b] = E_i[p^a] E_j[g^b].
// mean_f = mp2 - 2 mp mg + mg2
// E[d^2]_f = mp4 - 4 mp3 mg + 6 mp2 mg2 - 4 mp mg3 + mg4 ; var = E[d^2]-mean^2
// ---------------------------------------------------------------------------
__global__ void stats_kernel(const float* __restrict__ probe,
                             const float* __restrict__ gallery,
                             const float* __restrict__ gamma,
                             const float* __restrict__ beta)
{
    int f = blockIdx.x * blockDim.x + threadIdx.x;
    if (f >= FEAT) return;
    double p1 = 0, p2 = 0, p3 = 0, p4 = 0;
    for (int i = 0; i < NP; i++) {
        double x = (double)probe[i * FEAT + f];
        double x2 = x * x;
        p1 += x; p2 += x2; p3 += x2 * x; p4 += x2 * x2;
    }
    p1 *= (1.0 / NP); p2 *= (1.0 / NP); p3 *= (1.0 / NP); p4 *= (1.0 / NP);
    double g1 = 0, g2 = 0, g3 = 0, g4 = 0;
    for (int j = 0; j < NG; j++) {
        double x = (double)gallery[j * FEAT + f];
        double x2 = x * x;
        g1 += x; g2 += x2; g3 += x2 * x; g4 += x2 * x2;
    }
    g1 *= (1.0 / NG); g2 *= (1.0 / NG); g3 *= (1.0 / NG); g4 *= (1.0 / NG);

    double mean = p2 - 2.0 * p1 * g1 + g2;
    double ed2  = p4 - 4.0 * p3 * g1 + 6.0 * p2 * g2 - 4.0 * p1 * g3 + g4;
    double var  = ed2 - mean * mean;
    double s    = (double)gamma[f] / sqrt(var + EPSV);
    d_scale[f] = (float)s;
    d_shift[f] = (float)((double)beta[f] - mean * s);
}

// ---------------------------------------------------------------------------
// Stage B: W' = W * scale ; C[c] = b[c] + sum_f shift[f]*W[c,f]
// ---------------------------------------------------------------------------
__global__ void prep_kernel(const float* __restrict__ W,
                            const float* __restrict__ b)
{
    int c = blockIdx.x;
    int t = threadIdx.x;
    float acc = 0.f;
    for (int f = t; f < FEAT; f += 256) {
        float w = W[c * FEAT + f];
        d_Wp[c * FEAT + f] = w * d_scale[f];
        acc += w * d_shift[f];
    }
    __shared__ float red[256];
    red[t] = acc;
    __syncthreads();
    for (int s = 128; s > 0; s >>= 1) {
        if (t < s) red[t] += red[t + s];
        __syncthreads();
    }
    if (t == 0) d_C[c] = b[c] + red[0];
}

// ---------------------------------------------------------------------------
// Stage C: main GEMM. out[n,c] = sum_f (p[i,f]-g[j,f])^2 * Wp[c,f] + C[c]
// 128x128 block tile, 8x8 microtile/thread, packed f32x2 FMA (sm_103a).
// ---------------------------------------------------------------------------
__device__ __forceinline__ void ffma2(unsigned long long& d,
                                      unsigned long long a,
                                      unsigned long long b)
{
    asm("fma.rn.f32x2 %0, %1, %2, %0;" : "+l"(d) : "l"(a), "l"(b));
}
__device__ __forceinline__ unsigned long long pack2(float lo, float hi)
{
    unsigned long long r;
    asm("mov.b64 %0, {%1, %2};" : "=l"(r) : "f"(lo), "f"(hi));
    return r;
}
__device__ __forceinline__ float2 unpack2(unsigned long long v)
{
    float2 r;
    asm("mov.b64 {%0, %1}, %2;" : "=f"(r.x), "=f"(r.y) : "l"(v));
    return r;
}

struct Fetch { float4 p, g0, g1, w0, w1; };

__device__ __forceinline__ Fetch load_tile(const float* __restrict__ pRow,
                                           const float* __restrict__ gRow0,
                                           const float* __restrict__ wRow0,
                                           bool w1ok, int k0, int lk)
{
    Fetch f;
    f.p  = *(const float4*)(pRow  + k0 + lk);
    f.g0 = *(const float4*)(gRow0 + k0 + lk);
    f.g1 = *(const float4*)(gRow0 + 64 * FEAT + k0 + lk);
    f.w0 = *(const float4*)(wRow0 + k0 + lk);
    f.w1 = w1ok ? *(const float4*)(wRow0 + 64 * FEAT + k0 + lk)
                : make_float4(0.f, 0.f, 0.f, 0.f);
    return f;
}

__global__ __launch_bounds__(256)
void gemm_kernel(const float* __restrict__ probe,
                 const float* __restrict__ gallery,
                 float* __restrict__ out)
{
    __shared__ float As[TK][LDA];   // d-tile:  [k][n]
    __shared__ float Bs[TK][LDA];   // W'-tile: [k][c]

    const int tid   = threadIdx.x;
    const int ctile = blockIdx.x;          // 0..5
    const int ntile = blockIdx.y;          // 0..127
    const int nbase = ntile * TN;
    const int iProbe = nbase / NG;         // fixed probe row for this tile
    const int jbase  = nbase % NG;
    const int cbase  = ctile * TCc;

    // global-load mapping: 64 rows x 4 k-quads, two halves
    const int ln = tid >> 2;               // 0..63
    const int lk = (tid & 3) << 2;         // 0,4,8,12

    // compute mapping: warp covers 4 c-groups x 8 n-groups (low LDS traffic)
    const int w    = tid >> 5;
    const int lane = tid & 31;
    const int tx = (lane & 3) + ((w & 3) << 2);   // 0..15 -> c-group
    const int ty = (lane >> 2) + ((w >> 2) << 3); // 0..15 -> n-group

    const float* pRow  = probe + (size_t)iProbe * FEAT;
    const float* gRow0 = gallery + (size_t)(jbase + ln) * FEAT;
    const int c0 = cbase + ln;                    // always < NCLS (<=703)
    const int c1 = c0 + 64;
    const float* wRow0 = d_Wp + (size_t)c0 * FEAT;
    const bool w1ok = (c1 < NCLS);

    unsigned long long acc[8][4];
    #pragma unroll
    for (int m = 0; m < 8; m++)
        #pragma unroll
        for (int q = 0; q < 4; q++) acc[m][q] = 0ull;

    Fetch f = load_tile(pRow, gRow0, wRow0, w1ok, 0, lk);

    for (int k0 = 0; k0 < FEAT; k0 += TK) {
        __syncthreads();
        // store d = (p-g)^2 and W' into SMEM
        float dd;
        dd = f.p.x - f.g0.x; As[lk + 0][ln]      = dd * dd;
        dd = f.p.y - f.g0.y; As[lk + 1][ln]      = dd * dd;
        dd = f.p.z - f.g0.z; As[lk + 2][ln]      = dd * dd;
        dd = f.p.w - f.g0.w; As[lk + 3][ln]      = dd * dd;
        dd = f.p.x - f.g1.x; As[lk + 0][ln + 64] = dd * dd;
        dd = f.p.y - f.g1.y; As[lk + 1][ln + 64] = dd * dd;
        dd = f.p.z - f.g1.z; As[lk + 2][ln + 64] = dd * dd;
        dd = f.p.w - f.g1.w; As[lk + 3][ln + 64] = dd * dd;
        Bs[lk + 0][ln]      = f.w0.x;
        Bs[lk + 1][ln]      = f.w0.y;
        Bs[lk + 2][ln]      = f.w0.z;
        Bs[lk + 3][ln]      = f.w0.w;
        Bs[lk + 0][ln + 64] = f.w1.x;
        Bs[lk + 1][ln + 64] = f.w1.y;
        Bs[lk + 2][ln + 64] = f.w1.z;
        Bs[lk + 3][ln + 64] = f.w1.w;
        __syncthreads();

        // prefetch next k-slice while computing this one
        if (k0 + TK < FEAT)
            f = load_tile(pRow, gRow0, wRow0, w1ok, k0 + TK, lk);

        #pragma unroll
        for (int k = 0; k < TK; k++) {
            const float4 aLo = *(const float4*)&As[k][(ty << 3)];
            const float4 aHi = *(const float4*)&As[k][(ty << 3) + 4];
            const float4 bLo = *(const float4*)&Bs[k][(tx << 3)];
            const float4 bHi = *(const float4*)&Bs[k][(tx << 3) + 4];
            unsigned long long b2[4];
            b2[0] = pack2(bLo.x, bLo.y);
            b2[1] = pack2(bLo.z, bLo.w);
            b2[2] = pack2(bHi.x, bHi.y);
            b2[3] = pack2(bHi.z, bHi.w);
            const float av[8] = {aLo.x, aLo.y, aLo.z, aLo.w,
                                 aHi.x, aHi.y, aHi.z, aHi.w};
            #pragma unroll
            for (int m = 0; m < 8; m++) {
                const unsigned long long a2 = pack2(av[m], av[m]);
                ffma2(acc[m][0], a2, b2[0]);
                ffma2(acc[m][1], a2, b2[1]);
                ffma2(acc[m][2], a2, b2[2]);
                ffma2(acc[m][3], a2, b2[3]);
            }
        }
    }

    // epilogue: add per-class constant, guarded store
    const int ccol = cbase + (tx << 3);
    float Cc[8];
    #pragma unroll
    for (int cc = 0; cc < 8; cc++)
        Cc[cc] = (ccol + cc < NCLS) ? d_C[ccol + cc] : 0.f;

    const int nrow = nbase + (ty << 3);
    #pragma unroll
    for (int m = 0; m < 8; m++) {
        float* orow = out + (size_t)(nrow + m) * NCLS + ccol;
        #pragma unroll
        for (int q = 0; q < 4; q++) {
            const float2 v = unpack2(acc[m][q]);
            if (ccol + 2 * q     < NCLS) orow[2 * q]     = v.x + Cc[2 * q];
            if (ccol + 2 * q + 1 < NCLS) orow[2 * q + 1] = v.y + Cc[2 * q + 1];
        }
    }
}

// ---------------------------------------------------------------------------
extern "C" void kernel_launch(void* const* d_in, const int* in_sizes, int n_in,
                              void* d_out, int out_size)
{
    const float* probe   = (const float*)d_in[0];
    const float* gallery = (const float*)d_in[1];
    const float* gamma   = (const float*)d_in[2];
    const float* beta    = (const float*)d_in[3];
    const float* W       = (const float*)d_in[4];
    const float* b       = (const float*)d_in[5];
    float* out = (float*)d_out;

    stats_kernel<<<FEAT / 256, 256>>>(probe, gallery, gamma, beta);
    prep_kernel<<<NCLS, 256>>>(W, b);
    dim3 grid((NCLS + TCc - 1) / TCc, (NP * NG) / TN);  // (6, 128)
    gemm_kernel<<<grid, 256>>>(probe, gallery, out);
}

// round 4
// speedup vs baseline: 2.1154x; 2.1154x over previous
#include <cuda_runtime.h>
#include <cuda_fp16.h>
#include <cstdint>
#include <cstring>

#define FEAT 2048
#define NCLS 751
#define NCLSP 768          // padded classes (6 tiles of 128)
#define NP   64
#define NG   256
#define EPSV 1e-5f
#define WSCALE 512.0f      // W' prescale (keeps fp16 normal range)
#define OSCALE (1.0f / 512.0f)

// GEMM tiling
#define TM   128           // n-rows per CTA (2 probes x 64 gallery)
#define TNC  128           // classes per CTA
#define KT   64            // k-slice per stage
#define KITERS (FEAT / KT) // 32

// SMEM: per stage: Ah 16K | Al 16K | B 16K = 48K; x2 stages + 1K align pad
#define STAGE_BYTES 49152
#define SMEM_TOTAL (2 * STAGE_BYTES + 1024)

// --------------------------- device scratch --------------------------------
__device__ float d_scale[FEAT];
__device__ float d_shift[FEAT];
__device__ float d_C[NCLSP];
__device__ uint4 d_Wp16[NCLSP * (FEAT / 8)];   // fp16 W'*512, 8 halves/uint4

// --------------------------- helpers ----------------------------------------
__device__ __forceinline__ uint32_t smem_u32(const void* p) {
    uint32_t a;
    asm("{ .reg .u64 t; cvta.to.shared.u64 t, %1; cvt.u32.u64 %0, t; }"
        : "=r"(a) : "l"(p));
    return a;
}
__device__ __forceinline__ void ldsm4(uint32_t* r, uint32_t addr) {
    asm volatile("ldmatrix.sync.aligned.m8n8.x4.shared.b16 {%0,%1,%2,%3}, [%4];"
                 : "=r"(r[0]), "=r"(r[1]), "=r"(r[2]), "=r"(r[3]) : "r"(addr));
}
__device__ __forceinline__ void ldsm2(uint32_t* r, uint32_t addr) {
    asm volatile("ldmatrix.sync.aligned.m8n8.x2.shared.b16 {%0,%1}, [%2];"
                 : "=r"(r[0]), "=r"(r[1]) : "r"(addr));
}
__device__ __forceinline__ void mma16816(float* c, const uint32_t* a,
                                         const uint32_t* b) {
    asm volatile(
        "mma.sync.aligned.m16n8k16.row.col.f32.f16.f16.f32 "
        "{%0,%1,%2,%3}, {%4,%5,%6,%7}, {%8,%9}, {%0,%1,%2,%3};"
        : "+f"(c[0]), "+f"(c[1]), "+f"(c[2]), "+f"(c[3])
        : "r"(a[0]), "r"(a[1]), "r"(a[2]), "r"(a[3]), "r"(b[0]), "r"(b[1]));
}
__device__ __forceinline__ uint32_t h2u(__half2 h) {
    uint32_t u; memcpy(&u, &h, 4); return u;
}
// fp16 hi/lo split of a pair of floats
__device__ __forceinline__ void split2(float v0, float v1,
                                       uint32_t& hi, uint32_t& lo) {
    __half2 h = __float22half2_rn(make_float2(v0, v1));
    float2 hf = __half22float2(h);
    __half2 l = __float22half2_rn(make_float2(v0 - hf.x, v1 - hf.y));
    hi = h2u(h); lo = h2u(l);
}
__device__ __forceinline__ uint32_t pack16(float v0, float v1) {
    return h2u(__float22half2_rn(make_float2(v0, v1)));
}

// ---------------------------------------------------------------------------
// Stage A: exact batch stats from per-feature moments (fp32; FP64 was 144us)
// ---------------------------------------------------------------------------
__global__ void stats_kernel(const float* __restrict__ probe,
                             const float* __restrict__ gallery,
                             const float* __restrict__ gamma,
                             const float* __restrict__ beta)
{
    int f = blockIdx.x * blockDim.x + threadIdx.x;
    if (f >= FEAT) return;
    float p1 = 0, p2 = 0, p3 = 0, p4 = 0;
    #pragma unroll 8
    for (int i = 0; i < NP; i++) {
        float x = probe[i * FEAT + f];
        float x2 = x * x;
        p1 += x; p2 += x2; p3 += x2 * x; p4 += x2 * x2;
    }
    p1 *= (1.f / NP); p2 *= (1.f / NP); p3 *= (1.f / NP); p4 *= (1.f / NP);
    float g1 = 0, g2 = 0, g3 = 0, g4 = 0;
    #pragma unroll 8
    for (int j = 0; j < NG; j++) {
        float x = gallery[j * FEAT + f];
        float x2 = x * x;
        g1 += x; g2 += x2; g3 += x2 * x; g4 += x2 * x2;
    }
    g1 *= (1.f / NG); g2 *= (1.f / NG); g3 *= (1.f / NG); g4 *= (1.f / NG);

    float mean = p2 - 2.f * p1 * g1 + g2;
    float ed2  = p4 - 4.f * p3 * g1 + 6.f * p2 * g2 - 4.f * p1 * g3 + g4;
    float var  = ed2 - mean * mean;
    float s    = gamma[f] * rsqrtf(var + EPSV);
    d_scale[f] = s;
    d_shift[f] = beta[f] - mean * s;
}

// ---------------------------------------------------------------------------
// Stage B: W'[c] = W[c]*scale*512 -> fp16 ; C[c] = b[c] + shift . W[c]
// padded rows [751,768) zero-filled.
// ---------------------------------------------------------------------------
__global__ void prep_kernel(const float* __restrict__ W,
                            const float* __restrict__ b)
{
    int c = blockIdx.x;
    int t = threadIdx.x;
    if (c >= NCLS) {
        d_Wp16[c * 256 + t] = make_uint4(0, 0, 0, 0);
        if (t == 0) d_C[c] = 0.f;
        return;
    }
    int f0 = t * 8;
    const float4* wp = (const float4*)(W + (size_t)c * FEAT + f0);
    const float4* sp = (const float4*)(d_scale + f0);
    const float4* hp = (const float4*)(d_shift + f0);
    float4 w0 = wp[0], w1 = wp[1];
    float4 s0 = sp[0], s1 = sp[1];
    float4 h0 = hp[0], h1 = hp[1];

    float v0 = w0.x * s0.x * WSCALE, v1 = w0.y * s0.y * WSCALE;
    float v2 = w0.z * s0.z * WSCALE, v3 = w0.w * s0.w * WSCALE;
    float v4 = w1.x * s1.x * WSCALE, v5 = w1.y * s1.y * WSCALE;
    float v6 = w1.z * s1.z * WSCALE, v7 = w1.w * s1.w * WSCALE;
    d_Wp16[c * 256 + t] = make_uint4(pack16(v0, v1), pack16(v2, v3),
                                     pack16(v4, v5), pack16(v6, v7));

    float acc = w0.x*h0.x + w0.y*h0.y + w0.z*h0.z + w0.w*h0.w
              + w1.x*h1.x + w1.y*h1.y + w1.z*h1.z + w1.w*h1.w;
    #pragma unroll
    for (int o = 16; o > 0; o >>= 1)
        acc += __shfl_down_sync(0xFFFFFFFFu, acc, o);
    __shared__ float red[8];
    if ((t & 31) == 0) red[t >> 5] = acc;
    __syncthreads();
    if (t == 0) {
        float s = 0.f;
        #pragma unroll
        for (int w = 0; w < 8; w++) s += red[w];
        d_C[c] = b[c] + s;
    }
}

// ---------------------------------------------------------------------------
// Stage C: mma.sync fp16 GEMM with A hi/lo split.
// out[n,c] = (sum_f d_hi/lo[n,f] * W16[c,f]) / 512 + C[c]
// ---------------------------------------------------------------------------
__global__ __launch_bounds__(256, 1)
void gemm_kernel(const float* __restrict__ probe,
                 const float* __restrict__ gallery,
                 float* __restrict__ out)
{
    extern __shared__ char smem_raw[];
    char* smem = (char*)(((uintptr_t)smem_raw + 1023) & ~(uintptr_t)1023);
    const uint32_t sbase = smem_u32(smem);

    const int tid  = threadIdx.x;
    const int wid  = tid >> 5;
    const int lane = tid & 31;

    const int by    = blockIdx.y;           // 0..127
    const int ibase = (by >> 2) * 2;        // probe pair base
    const int jbase = (by & 3) * 64;        // gallery base
    const int cbase = blockIdx.x * TNC;     // class base (<= 640)

    // ---- conversion mapping: thread -> (tile row r, k-half h) ----
    const int r    = tid >> 1;              // 0..127
    const int h    = tid & 1;
    const int col0 = h * 32;

    const float* gRow = gallery + (size_t)(jbase + (r & 63)) * FEAT + col0;
    const float* pRow = probe   + (size_t)(ibase + (r >> 6)) * FEAT + col0;
    const size_t wRowBase = (size_t)(cbase + r) * 256;  // uint4 units
    const uint32_t cvtOff = (uint32_t)(r * 128 + col0 * 2);

    // ---- mma mapping: warp grid 2(m) x 4(n); warp tile 64x32 ----
    const int m0 = (wid >> 2) * 64;
    const int n0 = (wid & 3) * 32;
    const int xr = (lane & 7) * 16;                     // swizzle XOR
    uint32_t arow[4], brow[4], akb[4], bkb[4];
    #pragma unroll
    for (int mt = 0; mt < 4; mt++)
        arow[mt] = (uint32_t)((m0 + mt * 16 + (lane & 15)) * 128);
    #pragma unroll
    for (int nt = 0; nt < 4; nt++)
        brow[nt] = (uint32_t)(32768 + (n0 + nt * 8 + (lane & 7)) * 128);
    #pragma unroll
    for (int kk = 0; kk < 4; kk++) {
        akb[kk] = (uint32_t)((kk * 32 + (lane >> 4) * 16) ^ xr);
        bkb[kk] = (uint32_t)((kk * 32 + ((lane >> 3) & 1) * 16) ^ xr);
    }

    float acc[4][4][4];
    #pragma unroll
    for (int mt = 0; mt < 4; mt++)
        #pragma unroll
        for (int nt = 0; nt < 4; nt++)
            #pragma unroll
            for (int q = 0; q < 4; q++) acc[mt][nt][q] = 0.f;

    // staged (converted) data for next stage
    uint4 HI[4], LO[4], WB[4];

    // ---- prologue: load + convert stage 0 ----
    {
        const float4* gp = (const float4*)gRow;
        const float4* pp = (const float4*)pRow;
        float4 Gv[8], Pv[8];
        #pragma unroll
        for (int q = 0; q < 8; q++) { Gv[q] = gp[q]; Pv[q] = pp[q]; }
        const uint4* wp = d_Wp16 + wRowBase + col0 / 8;
        #pragma unroll
        for (int q = 0; q < 4; q++) WB[q] = wp[q];
        #pragma unroll
        for (int q = 0; q < 4; q++) {
            float4 pa = Pv[2*q], ga = Gv[2*q], pb = Pv[2*q+1], gb = Gv[2*q+1];
            float v0 = pa.x - ga.x; v0 *= v0;
            float v1 = pa.y - ga.y; v1 *= v1;
            float v2 = pa.z - ga.z; v2 *= v2;
            float v3 = pa.w - ga.w; v3 *= v3;
            float v4 = pb.x - gb.x; v4 *= v4;
            float v5 = pb.y - gb.y; v5 *= v5;
            float v6 = pb.z - gb.z; v6 *= v6;
            float v7 = pb.w - gb.w; v7 *= v7;
            split2(v0, v1, HI[q].x, LO[q].x);
            split2(v2, v3, HI[q].y, LO[q].y);
            split2(v4, v5, HI[q].z, LO[q].z);
            split2(v6, v7, HI[q].w, LO[q].w);
        }
    }

    const uint32_t swzOff = cvtOff ^ ((cvtOff >> 3) & 0x70u);

    for (int kt = 0; kt < KITERS; kt++) {
        const int buf = kt & 1;
        char* st = smem + buf * STAGE_BYTES;

        // store staged tiles (swizzled)
        #pragma unroll
        for (int q = 0; q < 4; q++) {
            // chunk offsets stay within the 128B row: swizzle is additive here
            const uint32_t sw = swzOff ^ (uint32_t)(q * 16 ? 0 : 0);
            const uint32_t off = (cvtOff + q * 16);
            const uint32_t swz = off ^ ((off >> 3) & 0x70u);
            (void)sw;
            *(uint4*)(st + swz)         = HI[q];
            *(uint4*)(st + 16384 + swz) = LO[q];
            *(uint4*)(st + 32768 + swz) = WB[q];
        }
        __syncthreads();

        const bool more = (kt + 1 < KITERS);
        float4 Gv[8], Pv[8];
        if (more) {
            const int k1 = (kt + 1) * KT;
            const float4* gp = (const float4*)(gRow + k1);
            const float4* pp = (const float4*)(pRow + k1);
            #pragma unroll
            for (int q = 0; q < 8; q++) { Gv[q] = gp[q]; Pv[q] = pp[q]; }
            const uint4* wp = d_Wp16 + wRowBase + (k1 + col0) / 8;
            #pragma unroll
            for (int q = 0; q < 4; q++) WB[q] = wp[q];
        }

        // ---- MMA over this stage ----
        const uint32_t sb = sbase + buf * STAGE_BYTES;
        #pragma unroll
        for (int kk = 0; kk < 4; kk++) {
            uint32_t bfrag[4][2];
            #pragma unroll
            for (int nt = 0; nt < 4; nt++)
                ldsm2(bfrag[nt], sb + brow[nt] + bkb[kk]);
            #pragma unroll
            for (int mt = 0; mt < 4; mt++) {
                uint32_t ah[4], al[4];
                ldsm4(ah, sb + arow[mt] + akb[kk]);
                ldsm4(al, sb + 16384 + arow[mt] + akb[kk]);
                #pragma unroll
                for (int nt = 0; nt < 4; nt++) {
                    mma16816(acc[mt][nt], ah, bfrag[nt]);
                    mma16816(acc[mt][nt], al, bfrag[nt]);
                }
            }
        }

        // ---- convert next stage (LDG latency hidden by MMA above) ----
        if (more) {
            #pragma unroll
            for (int q = 0; q < 4; q++) {
                float4 pa = Pv[2*q], ga = Gv[2*q], pb = Pv[2*q+1], gb = Gv[2*q+1];
                float v0 = pa.x - ga.x; v0 *= v0;
                float v1 = pa.y - ga.y; v1 *= v1;
                float v2 = pa.z - ga.z; v2 *= v2;
                float v3 = pa.w - ga.w; v3 *= v3;
                float v4 = pb.x - gb.x; v4 *= v4;
                float v5 = pb.y - gb.y; v5 *= v5;
                float v6 = pb.z - gb.z; v6 *= v6;
                float v7 = pb.w - gb.w; v7 *= v7;
                split2(v0, v1, HI[q].x, LO[q].x);
                split2(v2, v3, HI[q].y, LO[q].y);
                split2(v4, v5, HI[q].z, LO[q].z);
                split2(v6, v7, HI[q].w, LO[q].w);
            }
        }
    }

    // ---- epilogue: direct register -> gmem, add C, unscale ----
    #pragma unroll
    for (int mt = 0; mt < 4; mt++) {
        const int mlA = m0 + mt * 16 + (lane >> 2);
        const int mlB = mlA + 8;
        const size_t nA = (size_t)((ibase + (mlA >> 6)) * NG + jbase + (mlA & 63));
        const size_t nB = (size_t)((ibase + (mlB >> 6)) * NG + jbase + (mlB & 63));
        #pragma unroll
        for (int nt = 0; nt < 4; nt++) {
            const int c = cbase + n0 + nt * 8 + (lane & 3) * 2;
            const float* a = acc[mt][nt];
            if (c < NCLS) {
                const float Cc = d_C[c];
                out[nA * NCLS + c] = a[0] * OSCALE + Cc;
                out[nB * NCLS + c] = a[2] * OSCALE + Cc;
            }
            if (c + 1 < NCLS) {
                const float Cc = d_C[c + 1];
                out[nA * NCLS + c + 1] = a[1] * OSCALE + Cc;
                out[nB * NCLS + c + 1] = a[3] * OSCALE + Cc;
            }
        }
    }
}

// ---------------------------------------------------------------------------
extern "C" void kernel_launch(void* const* d_in, const int* in_sizes, int n_in,
                              void* d_out, int out_size)
{
    const float* probe   = (const float*)d_in[0];
    const float* gallery = (const float*)d_in[1];
    const float* gamma   = (const float*)d_in[2];
    const float* beta    = (const float*)d_in[3];
    const float* W       = (const float*)d_in[4];
    const float* b       = (const float*)d_in[5];
    float* out = (float*)d_out;

    static bool attr_set = false;
    if (!attr_set) {
        cudaFuncSetAttribute(gemm_kernel,
                             cudaFuncAttributeMaxDynamicSharedMemorySize,
                             SMEM_TOTAL);
        attr_set = true;
    }

    stats_kernel<<<FEAT / 256, 256>>>(probe, gallery, gamma, beta);
    prep_kernel<<<NCLSP, 256>>>(W, b);
    dim3 grid(NCLSP / TNC, (NP * NG) / TM);   // (6, 128)
    gemm_kernel<<<grid, 256, SMEM_TOTAL>>>(probe, gallery, out);
}

// round 5
// speedup vs baseline: 2.6515x; 1.2534x over previous
#include <cuda_runtime.h>
#include <cuda_fp16.h>
#include <cstdint>
#include <cstring>

#define FEAT 2048
#define NCLS 751
#define NCLSP 768          // padded classes (6 tiles of 128)
#define NP   64
#define NG   256
#define EPSV 1e-5f
#define WSCALE 512.0f      // W' prescale (keeps fp16 normal range)
#define OSCALE (1.0f / 512.0f)

// GEMM tiling
#define TM   128           // n-rows per CTA (2 probes x 64 gallery)
#define TNC  128           // classes per CTA
#define KT   64            // k-slice per stage
#define KITERS (FEAT / KT) // 32

// SMEM: per stage: A 16K | B 16K = 32K; x2 stages + 1K align pad
#define STAGE_BYTES 32768
#define SMEM_TOTAL (2 * STAGE_BYTES + 1024)

// --------------------------- device scratch --------------------------------
__device__ float d_scale[FEAT];
__device__ float d_shift[FEAT];
__device__ float d_C[NCLSP];
__device__ uint4 d_Wp16[NCLSP * (FEAT / 8)];   // fp16 W'*512, 8 halves/uint4

// --------------------------- helpers ----------------------------------------
__device__ __forceinline__ uint32_t smem_u32(const void* p) {
    uint32_t a;
    asm("{ .reg .u64 t; cvta.to.shared.u64 t, %1; cvt.u32.u64 %0, t; }"
        : "=r"(a) : "l"(p));
    return a;
}
__device__ __forceinline__ void ldsm4(uint32_t* r, uint32_t addr) {
    asm volatile("ldmatrix.sync.aligned.m8n8.x4.shared.b16 {%0,%1,%2,%3}, [%4];"
                 : "=r"(r[0]), "=r"(r[1]), "=r"(r[2]), "=r"(r[3]) : "r"(addr));
}
__device__ __forceinline__ void ldsm2(uint32_t* r, uint32_t addr) {
    asm volatile("ldmatrix.sync.aligned.m8n8.x2.shared.b16 {%0,%1}, [%2];"
                 : "=r"(r[0]), "=r"(r[1]) : "r"(addr));
}
__device__ __forceinline__ void mma16816(float* c, const uint32_t* a,
                                         const uint32_t* b) {
    asm volatile(
        "mma.sync.aligned.m16n8k16.row.col.f32.f16.f16.f32 "
        "{%0,%1,%2,%3}, {%4,%5,%6,%7}, {%8,%9}, {%0,%1,%2,%3};"
        : "+f"(c[0]), "+f"(c[1]), "+f"(c[2]), "+f"(c[3])
        : "r"(a[0]), "r"(a[1]), "r"(a[2]), "r"(a[3]), "r"(b[0]), "r"(b[1]));
}
__device__ __forceinline__ uint32_t pack16(float v0, float v1) {
    __half2 h = __float22half2_rn(make_float2(v0, v1));
    uint32_t u; memcpy(&u, &h, 4); return u;
}
__device__ __forceinline__ void cp16(uint32_t dst, const void* src) {
    asm volatile("cp.async.cg.shared.global [%0], [%1], 16;"
                 :: "r"(dst), "l"(src) : "memory");
}
__device__ __forceinline__ void cp_commit() {
    asm volatile("cp.async.commit_group;" ::: "memory");
}
__device__ __forceinline__ void cp_wait0() {
    asm volatile("cp.async.wait_group 0;" ::: "memory");
}

// ---------------------------------------------------------------------------
// Stage A: exact batch stats from per-feature moments.
// 32 blocks x 256 thr; thread = (feature-in-64, row-slice 0..3); smem reduce.
// ---------------------------------------------------------------------------
__global__ void stats_kernel(const float* __restrict__ probe,
                             const float* __restrict__ gallery,
                             const float* __restrict__ gamma,
                             const float* __restrict__ beta)
{
    const int tx = threadIdx.x & 63;        // feature within block
    const int ty = threadIdx.x >> 6;        // row slice 0..3
    const int f  = blockIdx.x * 64 + tx;

    float p1 = 0, p2 = 0, p3 = 0, p4 = 0;
    #pragma unroll 4
    for (int i = ty * 16; i < ty * 16 + 16; i++) {
        float x = probe[i * FEAT + f];
        float x2 = x * x;
        p1 += x; p2 += x2; p3 += x2 * x; p4 += x2 * x2;
    }
    float g1 = 0, g2 = 0, g3 = 0, g4 = 0;
    #pragma unroll 4
    for (int j = ty * 64; j < ty * 64 + 64; j++) {
        float x = gallery[j * FEAT + f];
        float x2 = x * x;
        g1 += x; g2 += x2; g3 += x2 * x; g4 += x2 * x2;
    }

    __shared__ float red[8][4][64];
    red[0][ty][tx] = p1; red[1][ty][tx] = p2;
    red[2][ty][tx] = p3; red[3][ty][tx] = p4;
    red[4][ty][tx] = g1; red[5][ty][tx] = g2;
    red[6][ty][tx] = g3; red[7][ty][tx] = g4;
    __syncthreads();
    if (ty != 0) return;

    p1 = (red[0][0][tx] + red[0][1][tx] + red[0][2][tx] + red[0][3][tx]) * (1.f/NP);
    p2 = (red[1][0][tx] + red[1][1][tx] + red[1][2][tx] + red[1][3][tx]) * (1.f/NP);
    p3 = (red[2][0][tx] + red[2][1][tx] + red[2][2][tx] + red[2][3][tx]) * (1.f/NP);
    p4 = (red[3][0][tx] + red[3][1][tx] + red[3][2][tx] + red[3][3][tx]) * (1.f/NP);
    g1 = (red[4][0][tx] + red[4][1][tx] + red[4][2][tx] + red[4][3][tx]) * (1.f/NG);
    g2 = (red[5][0][tx] + red[5][1][tx] + red[5][2][tx] + red[5][3][tx]) * (1.f/NG);
    g3 = (red[6][0][tx] + red[6][1][tx] + red[6][2][tx] + red[6][3][tx]) * (1.f/NG);
    g4 = (red[7][0][tx] + red[7][1][tx] + red[7][2][tx] + red[7][3][tx]) * (1.f/NG);

    float mean = p2 - 2.f * p1 * g1 + g2;
    float ed2  = p4 - 4.f * p3 * g1 + 6.f * p2 * g2 - 4.f * p1 * g3 + g4;
    float var  = ed2 - mean * mean;
    float s    = gamma[f] * rsqrtf(var + EPSV);
    d_scale[f] = s;
    d_shift[f] = beta[f] - mean * s;
}

// ---------------------------------------------------------------------------
// Stage B: W'[c] = W[c]*scale*512 -> fp16 ; C[c] = b[c] + shift . W[c]
// padded rows [751,768) zero-filled.
// ---------------------------------------------------------------------------
__global__ void prep_kernel(const float* __restrict__ W,
                            const float* __restrict__ b)
{
    int c = blockIdx.x;
    int t = threadIdx.x;
    if (c >= NCLS) {
        d_Wp16[c * 256 + t] = make_uint4(0, 0, 0, 0);
        if (t == 0) d_C[c] = 0.f;
        return;
    }
    int f0 = t * 8;
    const float4* wp = (const float4*)(W + (size_t)c * FEAT + f0);
    const float4* sp = (const float4*)(d_scale + f0);
    const float4* hp = (const float4*)(d_shift + f0);
    float4 w0 = wp[0], w1 = wp[1];
    float4 s0 = sp[0], s1 = sp[1];
    float4 h0 = hp[0], h1 = hp[1];

    float v0 = w0.x * s0.x * WSCALE, v1 = w0.y * s0.y * WSCALE;
    float v2 = w0.z * s0.z * WSCALE, v3 = w0.w * s0.w * WSCALE;
    float v4 = w1.x * s1.x * WSCALE, v5 = w1.y * s1.y * WSCALE;
    float v6 = w1.z * s1.z * WSCALE, v7 = w1.w * s1.w * WSCALE;
    d_Wp16[c * 256 + t] = make_uint4(pack16(v0, v1), pack16(v2, v3),
                                     pack16(v4, v5), pack16(v6, v7));

    float acc = w0.x*h0.x + w0.y*h0.y + w0.z*h0.z + w0.w*h0.w
              + w1.x*h1.x + w1.y*h1.y + w1.z*h1.z + w1.w*h1.w;
    #pragma unroll
    for (int o = 16; o > 0; o >>= 1)
        acc += __shfl_down_sync(0xFFFFFFFFu, acc, o);
    __shared__ float red[8];
    if ((t & 31) == 0) red[t >> 5] = acc;
    __syncthreads();
    if (t == 0) {
        float s = 0.f;
        #pragma unroll
        for (int w = 0; w < 8; w++) s += red[w];
        d_C[c] = b[c] + s;
    }
}

// ---------------------------------------------------------------------------
// Stage C: mma.sync fp16 GEMM, single-MMA (A rn, W rn; err ~4e-4).
// out[n,c] = (sum_f d16[n,f] * W16[c,f]) / 512 + C[c]
// A converted on the fly; B streamed via cp.async.
// ---------------------------------------------------------------------------
__global__ __launch_bounds__(256, 1)
void gemm_kernel(const float* __restrict__ probe,
                 const float* __restrict__ gallery,
                 float* __restrict__ out)
{
    extern __shared__ char smem_raw[];
    char* smem = (char*)(((uintptr_t)smem_raw + 1023) & ~(uintptr_t)1023);
    const uint32_t sbase = smem_u32(smem);

    const int tid  = threadIdx.x;
    const int wid  = tid >> 5;
    const int lane = tid & 31;

    const int by    = blockIdx.y;           // 0..127
    const int ibase = (by >> 2) * 2;        // probe pair base
    const int jbase = (by & 3) * 64;        // gallery base
    const int cbase = blockIdx.x * TNC;     // class base (<= 640)

    // ---- staging mapping: thread -> (tile row r, k-half h) ----
    const int r    = tid >> 1;              // 0..127
    const int h    = tid & 1;
    const int col0 = h * 32;

    const float* gRow = gallery + (size_t)(jbase + (r & 63)) * FEAT + col0;
    const float* pRow = probe   + (size_t)(ibase + (r >> 6)) * FEAT + col0;
    const uint4* wRow = d_Wp16 + (size_t)(cbase + r) * 256 + col0 / 8;
    const uint32_t cvtOff = (uint32_t)(r * 128 + col0 * 2);
    // per-chunk swizzled offsets (q*16 within one 128B row)
    uint32_t swz[4];
    #pragma unroll
    for (int q = 0; q < 4; q++) {
        const uint32_t off = cvtOff + q * 16;
        swz[q] = off ^ ((off >> 3) & 0x70u);
    }

    // ---- mma mapping: warp grid 2(m) x 4(n); warp tile 64x32 ----
    const int m0 = (wid >> 2) * 64;
    const int n0 = (wid & 3) * 32;
    const int xr = (lane & 7) * 16;
    uint32_t arow[4], brow[4], akb[4], bkb[4];
    #pragma unroll
    for (int mt = 0; mt < 4; mt++)
        arow[mt] = (uint32_t)((m0 + mt * 16 + (lane & 15)) * 128);
    #pragma unroll
    for (int nt = 0; nt < 4; nt++)
        brow[nt] = (uint32_t)(16384 + (n0 + nt * 8 + (lane & 7)) * 128);
    #pragma unroll
    for (int kk = 0; kk < 4; kk++) {
        akb[kk] = (uint32_t)((kk * 32 + (lane >> 4) * 16) ^ xr);
        bkb[kk] = (uint32_t)((kk * 32 + ((lane >> 3) & 1) * 16) ^ xr);
    }

    float acc[4][4][4];
    #pragma unroll
    for (int mt = 0; mt < 4; mt++)
        #pragma unroll
        for (int nt = 0; nt < 4; nt++)
            #pragma unroll
            for (int q = 0; q < 4; q++) acc[mt][nt][q] = 0.f;

    uint4 HI[4];

    // ---- prologue: cp.async B0, load+convert A0 ----
    {
        const uint32_t bdst = sbase + 16384;
        #pragma unroll
        for (int q = 0; q < 4; q++) cp16(bdst + swz[q], wRow + q);
        cp_commit();

        const float4* gp = (const float4*)gRow;
        const float4* pp = (const float4*)pRow;
        #pragma unroll
        for (int q = 0; q < 4; q++) {
            float4 pa = pp[2*q], ga = gp[2*q], pb = pp[2*q+1], gb = gp[2*q+1];
            float v0 = pa.x - ga.x; v0 *= v0;
            float v1 = pa.y - ga.y; v1 *= v1;
            float v2 = pa.z - ga.z; v2 *= v2;
            float v3 = pa.w - ga.w; v3 *= v3;
            float v4 = pb.x - gb.x; v4 *= v4;
            float v5 = pb.y - gb.y; v5 *= v5;
            float v6 = pb.z - gb.z; v6 *= v6;
            float v7 = pb.w - gb.w; v7 *= v7;
            HI[q] = make_uint4(pack16(v0, v1), pack16(v2, v3),
                               pack16(v4, v5), pack16(v6, v7));
        }
    }

    for (int kt = 0; kt < KITERS; kt++) {
        const int buf = kt & 1;
        char* st = smem + buf * STAGE_BYTES;

        cp_wait0();                          // B(kt) resident
        #pragma unroll
        for (int q = 0; q < 4; q++)
            *(uint4*)(st + swz[q]) = HI[q];  // A(kt)
        __syncthreads();

        const bool more = (kt + 1 < KITERS);
        float4 Gv[8], Pv[8];
        if (more) {
            const int k1 = (kt + 1) * KT;
            // B(kt+1) into the other buffer
            const uint32_t bdst = sbase + (buf ^ 1) * STAGE_BYTES + 16384;
            const uint4* wp = wRow + k1 / 8;
            #pragma unroll
            for (int q = 0; q < 4; q++) cp16(bdst + swz[q], wp + q);
            cp_commit();
            const float4* gp = (const float4*)(gRow + k1);
            const float4* pp = (const float4*)(pRow + k1);
            #pragma unroll
            for (int q = 0; q < 8; q++) { Gv[q] = gp[q]; Pv[q] = pp[q]; }
        }

        // ---- MMA over this stage ----
        const uint32_t sb = sbase + buf * STAGE_BYTES;
        #pragma unroll
        for (int kk = 0; kk < 4; kk++) {
            uint32_t bfrag[4][2];
            #pragma unroll
            for (int nt = 0; nt < 4; nt++)
                ldsm2(bfrag[nt], sb + brow[nt] + bkb[kk]);
            #pragma unroll
            for (int mt = 0; mt < 4; mt++) {
                uint32_t ah[4];
                ldsm4(ah, sb + arow[mt] + akb[kk]);
                #pragma unroll
                for (int nt = 0; nt < 4; nt++)
                    mma16816(acc[mt][nt], ah, bfrag[nt]);
            }
        }

        // ---- convert next stage (LDG latency hidden by MMA above) ----
        if (more) {
            #pragma unroll
            for (int q = 0; q < 4; q++) {
                float4 pa = Pv[2*q], ga = Gv[2*q], pb = Pv[2*q+1], gb = Gv[2*q+1];
                float v0 = pa.x - ga.x; v0 *= v0;
                float v1 = pa.y - ga.y; v1 *= v1;
                float v2 = pa.z - ga.z; v2 *= v2;
                float v3 = pa.w - ga.w; v3 *= v3;
                float v4 = pb.x - gb.x; v4 *= v4;
                float v5 = pb.y - gb.y; v5 *= v5;
                float v6 = pb.z - gb.z; v6 *= v6;
                float v7 = pb.w - gb.w; v7 *= v7;
                HI[q] = make_uint4(pack16(v0, v1), pack16(v2, v3),
                                   pack16(v4, v5), pack16(v6, v7));
            }
        }
    }

    // ---- epilogue: direct register -> gmem, add C, unscale ----
    #pragma unroll
    for (int mt = 0; mt < 4; mt++) {
        const int mlA = m0 + mt * 16 + (lane >> 2);
        const int mlB = mlA + 8;
        const size_t nA = (size_t)((ibase + (mlA >> 6)) * NG + jbase + (mlA & 63));
        const size_t nB = (size_t)((ibase + (mlB >> 6)) * NG + jbase + (mlB & 63));
        #pragma unroll
        for (int nt = 0; nt < 4; nt++) {
            const int c = cbase + n0 + nt * 8 + (lane & 3) * 2;
            const float* a = acc[mt][nt];
            if (c < NCLS) {
                const float Cc = d_C[c];
                out[nA * NCLS + c] = a[0] * OSCALE + Cc;
                out[nB * NCLS + c] = a[2] * OSCALE + Cc;
            }
            if (c + 1 < NCLS) {
                const float Cc = d_C[c + 1];
                out[nA * NCLS + c + 1] = a[1] * OSCALE + Cc;
                out[nB * NCLS + c + 1] = a[3] * OSCALE + Cc;
            }
        }
    }
}

// ---------------------------------------------------------------------------
extern "C" void kernel_launch(void* const* d_in, const int* in_sizes, int n_in,
                              void* d_out, int out_size)
{
    const float* probe   = (const float*)d_in[0];
    const float* gallery = (const float*)d_in[1];
    const float* gamma   = (const float*)d_in[2];
    const float* beta    = (const float*)d_in[3];
    const float* W       = (const float*)d_in[4];
    const float* b       = (const float*)d_in[5];
    float* out = (float*)d_out;

    static bool attr_set = false;
    if (!attr_set) {
        cudaFuncSetAttribute(gemm_kernel,
                             cudaFuncAttributeMaxDynamicSharedMemorySize,
                             SMEM_TOTAL);
        attr_set = true;
    }

    stats_kernel<<<FEAT / 64, 256>>>(probe, gallery, gamma, beta);
    prep_kernel<<<NCLSP, 256>>>(W, b);
    dim3 grid(NCLSP / TNC, (NP * NG) / TM);   // (6, 128)
    gemm_kernel<<<grid, 256, SMEM_TOTAL>>>(probe, gallery, out);
}

// round 6
// speedup vs baseline: 4.9190x; 1.8552x over previous
#include <cuda_runtime.h>
#include <cuda_fp16.h>
#include <cstdint>
#include <cstring>

#define FEAT 2048
#define NCLS 751
#define NCLSP 768          // padded classes (6 tiles of 128)
#define NP   64
#define NG   256
#define NROWS (NP * NG)    // 16384
#define EPSV 1e-5f
#define WSCALE 512.0f      // W' prescale (keeps fp16 normal range)
#define OSCALE (1.0f / 512.0f)

// GEMM tiling
#define TM   128           // n-rows per CTA
#define TNC  128           // classes per CTA
#define KT   64            // k-slice per stage
#define KITERS (FEAT / KT) // 32

// SMEM: per stage: A 16K | B 16K = 32K; x2 stages + 1K align pad
#define STAGE_BYTES 32768
#define SMEM_TOTAL (2 * STAGE_BYTES + 1024)

// --------------------------- device scratch --------------------------------
__device__ float d_scale[FEAT];
__device__ float d_shift[FEAT];
__device__ float d_C[NCLSP];
__device__ uint4 d_Wp16[NCLSP * (FEAT / 8)];   // fp16 W'*512
__device__ uint4 d_A16[NROWS * (FEAT / 8)];    // fp16 d=(p-g)^2, 64MB

// --------------------------- helpers ----------------------------------------
__device__ __forceinline__ uint32_t smem_u32(const void* p) {
    uint32_t a;
    asm("{ .reg .u64 t; cvta.to.shared.u64 t, %1; cvt.u32.u64 %0, t; }"
        : "=r"(a) : "l"(p));
    return a;
}
__device__ __forceinline__ void ldsm4(uint32_t* r, uint32_t addr) {
    asm volatile("ldmatrix.sync.aligned.m8n8.x4.shared.b16 {%0,%1,%2,%3}, [%4];"
                 : "=r"(r[0]), "=r"(r[1]), "=r"(r[2]), "=r"(r[3]) : "r"(addr));
}
__device__ __forceinline__ void ldsm2(uint32_t* r, uint32_t addr) {
    asm volatile("ldmatrix.sync.aligned.m8n8.x2.shared.b16 {%0,%1}, [%2];"
                 : "=r"(r[0]), "=r"(r[1]) : "r"(addr));
}
__device__ __forceinline__ void mma16816(float* c, const uint32_t* a,
                                         const uint32_t* b) {
    asm volatile(
        "mma.sync.aligned.m16n8k16.row.col.f32.f16.f16.f32 "
        "{%0,%1,%2,%3}, {%4,%5,%6,%7}, {%8,%9}, {%0,%1,%2,%3};"
        : "+f"(c[0]), "+f"(c[1]), "+f"(c[2]), "+f"(c[3])
        : "r"(a[0]), "r"(a[1]), "r"(a[2]), "r"(a[3]), "r"(b[0]), "r"(b[1]));
}
__device__ __forceinline__ uint32_t pack16(float v0, float v1) {
    __half2 h = __float22half2_rn(make_float2(v0, v1));
    uint32_t u; memcpy(&u, &h, 4); return u;
}
__device__ __forceinline__ void cp16(uint32_t dst, const void* src) {
    asm volatile("cp.async.cg.shared.global [%0], [%1], 16;"
                 :: "r"(dst), "l"(src) : "memory");
}
__device__ __forceinline__ void cp_commit() {
    asm volatile("cp.async.commit_group;" ::: "memory");
}
__device__ __forceinline__ void cp_wait0() {
    asm volatile("cp.async.wait_group 0;" ::: "memory");
}

// ---------------------------------------------------------------------------
// Stage A: exact batch stats from per-feature moments.
// ---------------------------------------------------------------------------
__global__ void stats_kernel(const float* __restrict__ probe,
                             const float* __restrict__ gallery,
                             const float* __restrict__ gamma,
                             const float* __restrict__ beta)
{
    const int tx = threadIdx.x & 63;
    const int ty = threadIdx.x >> 6;
    const int f  = blockIdx.x * 64 + tx;

    float p1 = 0, p2 = 0, p3 = 0, p4 = 0;
    #pragma unroll 4
    for (int i = ty * 16; i < ty * 16 + 16; i++) {
        float x = probe[i * FEAT + f];
        float x2 = x * x;
        p1 += x; p2 += x2; p3 += x2 * x; p4 += x2 * x2;
    }
    float g1 = 0, g2 = 0, g3 = 0, g4 = 0;
    #pragma unroll 4
    for (int j = ty * 64; j < ty * 64 + 64; j++) {
        float x = gallery[j * FEAT + f];
        float x2 = x * x;
        g1 += x; g2 += x2; g3 += x2 * x; g4 += x2 * x2;
    }

    __shared__ float red[8][4][64];
    red[0][ty][tx] = p1; red[1][ty][tx] = p2;
    red[2][ty][tx] = p3; red[3][ty][tx] = p4;
    red[4][ty][tx] = g1; red[5][ty][tx] = g2;
    red[6][ty][tx] = g3; red[7][ty][tx] = g4;
    __syncthreads();
    if (ty != 0) return;

    p1 = (red[0][0][tx] + red[0][1][tx] + red[0][2][tx] + red[0][3][tx]) * (1.f/NP);
    p2 = (red[1][0][tx] + red[1][1][tx] + red[1][2][tx] + red[1][3][tx]) * (1.f/NP);
    p3 = (red[2][0][tx] + red[2][1][tx] + red[2][2][tx] + red[2][3][tx]) * (1.f/NP);
    p4 = (red[3][0][tx] + red[3][1][tx] + red[3][2][tx] + red[3][3][tx]) * (1.f/NP);
    g1 = (red[4][0][tx] + red[4][1][tx] + red[4][2][tx] + red[4][3][tx]) * (1.f/NG);
    g2 = (red[5][0][tx] + red[5][1][tx] + red[5][2][tx] + red[5][3][tx]) * (1.f/NG);
    g3 = (red[6][0][tx] + red[6][1][tx] + red[6][2][tx] + red[6][3][tx]) * (1.f/NG);
    g4 = (red[7][0][tx] + red[7][1][tx] + red[7][2][tx] + red[7][3][tx]) * (1.f/NG);

    float mean = p2 - 2.f * p1 * g1 + g2;
    float ed2  = p4 - 4.f * p3 * g1 + 6.f * p2 * g2 - 4.f * p1 * g3 + g4;
    float var  = ed2 - mean * mean;
    float s    = gamma[f] * rsqrtf(var + EPSV);
    d_scale[f] = s;
    d_shift[f] = beta[f] - mean * s;
}

// ---------------------------------------------------------------------------
// Stage A2: materialize A = (p-g)^2 as fp16 (row n = i*256+j, 256 uint4/row)
// ---------------------------------------------------------------------------
__global__ __launch_bounds__(256)
void build_kernel(const float* __restrict__ probe,
                  const float* __restrict__ gallery)
{
    const int n = blockIdx.x;
    const int t = threadIdx.x;
    const int i = n >> 8;
    const int j = n & 255;
    const float4* pp = (const float4*)(probe   + (size_t)i * FEAT) + t * 2;
    const float4* gp = (const float4*)(gallery + (size_t)j * FEAT) + t * 2;
    const float4 pa = pp[0], pb = pp[1], ga = gp[0], gb = gp[1];
    float v0 = pa.x - ga.x; v0 *= v0;
    float v1 = pa.y - ga.y; v1 *= v1;
    float v2 = pa.z - ga.z; v2 *= v2;
    float v3 = pa.w - ga.w; v3 *= v3;
    float v4 = pb.x - gb.x; v4 *= v4;
    float v5 = pb.y - gb.y; v5 *= v5;
    float v6 = pb.z - gb.z; v6 *= v6;
    float v7 = pb.w - gb.w; v7 *= v7;
    d_A16[(size_t)n * 256 + t] = make_uint4(pack16(v0, v1), pack16(v2, v3),
                                            pack16(v4, v5), pack16(v6, v7));
}

// ---------------------------------------------------------------------------
// Stage B: W'[c] = W[c]*scale*512 -> fp16 ; C[c] = b[c] + shift . W[c]
// ---------------------------------------------------------------------------
__global__ void prep_kernel(const float* __restrict__ W,
                            const float* __restrict__ b)
{
    int c = blockIdx.x;
    int t = threadIdx.x;
    if (c >= NCLS) {
        d_Wp16[c * 256 + t] = make_uint4(0, 0, 0, 0);
        if (t == 0) d_C[c] = 0.f;
        return;
    }
    int f0 = t * 8;
    const float4* wp = (const float4*)(W + (size_t)c * FEAT + f0);
    const float4* sp = (const float4*)(d_scale + f0);
    const float4* hp = (const float4*)(d_shift + f0);
    float4 w0 = wp[0], w1 = wp[1];
    float4 s0 = sp[0], s1 = sp[1];
    float4 h0 = hp[0], h1 = hp[1];

    float v0 = w0.x * s0.x * WSCALE, v1 = w0.y * s0.y * WSCALE;
    float v2 = w0.z * s0.z * WSCALE, v3 = w0.w * s0.w * WSCALE;
    float v4 = w1.x * s1.x * WSCALE, v5 = w1.y * s1.y * WSCALE;
    float v6 = w1.z * s1.z * WSCALE, v7 = w1.w * s1.w * WSCALE;
    d_Wp16[c * 256 + t] = make_uint4(pack16(v0, v1), pack16(v2, v3),
                                     pack16(v4, v5), pack16(v6, v7));

    float acc = w0.x*h0.x + w0.y*h0.y + w0.z*h0.z + w0.w*h0.w
              + w1.x*h1.x + w1.y*h1.y + w1.z*h1.z + w1.w*h1.w;
    #pragma unroll
    for (int o = 16; o > 0; o >>= 1)
        acc += __shfl_down_sync(0xFFFFFFFFu, acc, o);
    __shared__ float red[8];
    if ((t & 31) == 0) red[t >> 5] = acc;
    __syncthreads();
    if (t == 0) {
        float s = 0.f;
        #pragma unroll
        for (int w = 0; w < 8; w++) s += red[w];
        d_C[c] = b[c] + s;
    }
}

// ---------------------------------------------------------------------------
// Stage C: pure fp16 mma.sync GEMM, A and B both via cp.async.
// out[n,c] = (sum_f A16[n,f] * W16[c,f]) / 512 + C[c]
// ---------------------------------------------------------------------------
__global__ __launch_bounds__(256, 2)
void gemm_kernel(float* __restrict__ out)
{
    extern __shared__ char smem_raw[];
    char* smem = (char*)(((uintptr_t)smem_raw + 1023) & ~(uintptr_t)1023);
    const uint32_t sbase = smem_u32(smem);

    const int tid  = threadIdx.x;
    const int wid  = tid >> 5;
    const int lane = tid & 31;

    const int by    = blockIdx.y;
    const int ibase = (by >> 2) * 2;
    const int jbase = (by & 3) * 64;
    const int cbase = blockIdx.x * TNC;

    // ---- staging mapping: thread -> (tile row r, k-half h) ----
    const int r = tid >> 1;
    const int h = tid & 1;

    const int nrow = (ibase + (r >> 6)) * NG + jbase + (r & 63);
    const uint4* aRow = d_A16  + (size_t)nrow * 256 + h * 4;
    const uint4* wRow = d_Wp16 + (size_t)(cbase + r) * 256 + h * 4;

    const uint32_t cvtOff = (uint32_t)(r * 128 + h * 64);
    uint32_t swz[4];
    #pragma unroll
    for (int q = 0; q < 4; q++) {
        const uint32_t off = cvtOff + q * 16;
        swz[q] = off ^ ((off >> 3) & 0x70u);
    }

    // ---- mma mapping: warp grid 2(m) x 4(n); warp tile 64x32 ----
    const int m0 = (wid >> 2) * 64;
    const int n0 = (wid & 3) * 32;
    const int xr = (lane & 7) * 16;
    uint32_t arow[4], brow[4], akb[4], bkb[4];
    #pragma unroll
    for (int mt = 0; mt < 4; mt++)
        arow[mt] = (uint32_t)((m0 + mt * 16 + (lane & 15)) * 128);
    #pragma unroll
    for (int nt = 0; nt < 4; nt++)
        brow[nt] = (uint32_t)(16384 + (n0 + nt * 8 + (lane & 7)) * 128);
    #pragma unroll
    for (int kk = 0; kk < 4; kk++) {
        akb[kk] = (uint32_t)((kk * 32 + (lane >> 4) * 16) ^ xr);
        bkb[kk] = (uint32_t)((kk * 32 + ((lane >> 3) & 1) * 16) ^ xr);
    }

    float acc[4][4][4];
    #pragma unroll
    for (int mt = 0; mt < 4; mt++)
        #pragma unroll
        for (int nt = 0; nt < 4; nt++)
            #pragma unroll
            for (int q = 0; q < 4; q++) acc[mt][nt][q] = 0.f;

    // ---- prologue: stage 0 ----
    {
        const uint32_t ad = sbase;
        const uint32_t bd = sbase + 16384;
        #pragma unroll
        for (int q = 0; q < 4; q++) cp16(ad + swz[q], aRow + q);
        #pragma unroll
        for (int q = 0; q < 4; q++) cp16(bd + swz[q], wRow + q);
        cp_commit();
    }

    for (int kt = 0; kt < KITERS; kt++) {
        const int buf = kt & 1;

        cp_wait0();
        __syncthreads();

        if (kt + 1 < KITERS) {
            const uint32_t ad = sbase + (buf ^ 1) * STAGE_BYTES;
            const uint32_t bd = ad + 16384;
            const uint4* ap = aRow + (kt + 1) * 8;
            const uint4* wp = wRow + (kt + 1) * 8;
            #pragma unroll
            for (int q = 0; q < 4; q++) cp16(ad + swz[q], ap + q);
            #pragma unroll
            for (int q = 0; q < 4; q++) cp16(bd + swz[q], wp + q);
            cp_commit();
        }

        const uint32_t sb = sbase + buf * STAGE_BYTES;
        #pragma unroll
        for (int kk = 0; kk < 4; kk++) {
            uint32_t bfrag[4][2];
            #pragma unroll
            for (int nt = 0; nt < 4; nt++)
                ldsm2(bfrag[nt], sb + brow[nt] + bkb[kk]);
            #pragma unroll
            for (int mt = 0; mt < 4; mt++) {
                uint32_t ah[4];
                ldsm4(ah, sb + arow[mt] + akb[kk]);
                #pragma unroll
                for (int nt = 0; nt < 4; nt++)
                    mma16816(acc[mt][nt], ah, bfrag[nt]);
            }
        }
    }

    // ---- epilogue ----
    #pragma unroll
    for (int mt = 0; mt < 4; mt++) {
        const int mlA = m0 + mt * 16 + (lane >> 2);
        const int mlB = mlA + 8;
        const size_t nA = (size_t)((ibase + (mlA >> 6)) * NG + jbase + (mlA & 63));
        const size_t nB = (size_t)((ibase + (mlB >> 6)) * NG + jbase + (mlB & 63));
        #pragma unroll
        for (int nt = 0; nt < 4; nt++) {
            const int c = cbase + n0 + nt * 8 + (lane & 3) * 2;
            const float* a = acc[mt][nt];
            if (c < NCLS) {
                const float Cc = d_C[c];
                out[nA * NCLS + c] = a[0] * OSCALE + Cc;
                out[nB * NCLS + c] = a[2] * OSCALE + Cc;
            }
            if (c + 1 < NCLS) {
                const float Cc = d_C[c + 1];
                out[nA * NCLS + c + 1] = a[1] * OSCALE + Cc;
                out[nB * NCLS + c + 1] = a[3] * OSCALE + Cc;
            }
        }
    }
}

// ---------------------------------------------------------------------------
extern "C" void kernel_launch(void* const* d_in, const int* in_sizes, int n_in,
                              void* d_out, int out_size)
{
    const float* probe   = (const float*)d_in[0];
    const float* gallery = (const float*)d_in[1];
    const float* gamma   = (const float*)d_in[2];
    const float* beta    = (const float*)d_in[3];
    const float* W       = (const float*)d_in[4];
    const float* b       = (const float*)d_in[5];
    float* out = (float*)d_out;

    static bool attr_set = false;
    if (!attr_set) {
        cudaFuncSetAttribute(gemm_kernel,
                             cudaFuncAttributeMaxDynamicSharedMemorySize,
                             SMEM_TOTAL);
        attr_set = true;
    }

    stats_kernel<<<FEAT / 64, 256>>>(probe, gallery, gamma, beta);
    build_kernel<<<NROWS, 256>>>(probe, gallery);
    prep_kernel<<<NCLSP, 256>>>(W, b);
    dim3 grid(NCLSP / TNC, NROWS / TM);   // (6, 128)
    gemm_kernel<<<grid, 256, SMEM_TOTAL>>>(out);
}

// round 7
// speedup vs baseline: 5.2305x; 1.0633x over previous
#include <cuda_runtime.h>
#include <cuda_fp16.h>
#include <cstdint>
#include <cstring>

#define FEAT 2048
#define NCLS 751
#define NCLSP 768          // padded classes (6 tiles of 128)
#define NP   64
#define NG   256
#define NROWS (NP * NG)    // 16384
#define EPSV 1e-5f
#define WSCALE 512.0f
#define OSCALE (1.0f / 512.0f)

// GEMM tiling
#define TM   128
#define TNC  128
#define KT   64
#define KITERS (FEAT / KT) // 32

// SMEM: per stage: A 16K | B 16K = 32K; 3 stages + 1K align pad
#define STAGE_BYTES 32768
#define NSTAGE 3
#define SMEM_TOTAL (NSTAGE * STAGE_BYTES + 1024)

// --------------------------- device scratch --------------------------------
__device__ float d_scale[FEAT];
__device__ float d_shift[FEAT];
__device__ float d_C[NCLSP];
__device__ uint4 d_Wp16[NCLSP * (FEAT / 8)];   // fp16 W'*512
__device__ uint4 d_A16[NROWS * (FEAT / 8)];    // fp16 d=(p-g)^2, 64MB

// --------------------------- helpers ----------------------------------------
__device__ __forceinline__ uint32_t smem_u32(const void* p) {
    uint32_t a;
    asm("{ .reg .u64 t; cvta.to.shared.u64 t, %1; cvt.u32.u64 %0, t; }"
        : "=r"(a) : "l"(p));
    return a;
}
__device__ __forceinline__ void ldsm4(uint32_t* r, uint32_t addr) {
    asm volatile("ldmatrix.sync.aligned.m8n8.x4.shared.b16 {%0,%1,%2,%3}, [%4];"
                 : "=r"(r[0]), "=r"(r[1]), "=r"(r[2]), "=r"(r[3]) : "r"(addr));
}
__device__ __forceinline__ void mma16816(float* c, const uint32_t* a,
                                         const uint32_t* b) {
    asm volatile(
        "mma.sync.aligned.m16n8k16.row.col.f32.f16.f16.f32 "
        "{%0,%1,%2,%3}, {%4,%5,%6,%7}, {%8,%9}, {%0,%1,%2,%3};"
        : "+f"(c[0]), "+f"(c[1]), "+f"(c[2]), "+f"(c[3])
        : "r"(a[0]), "r"(a[1]), "r"(a[2]), "r"(a[3]), "r"(b[0]), "r"(b[1]));
}
__device__ __forceinline__ uint32_t pack16(float v0, float v1) {
    __half2 h = __float22half2_rn(make_float2(v0, v1));
    uint32_t u; memcpy(&u, &h, 4); return u;
}
__device__ __forceinline__ void cp16(uint32_t dst, const void* src) {
    asm volatile("cp.async.cg.shared.global [%0], [%1], 16;"
                 :: "r"(dst), "l"(src) : "memory");
}
__device__ __forceinline__ void cp_commit() {
    asm volatile("cp.async.commit_group;" ::: "memory");
}
__device__ __forceinline__ void cp_wait1() {
    asm volatile("cp.async.wait_group 1;" ::: "memory");
}

// ---------------------------------------------------------------------------
// Stage A: exact batch stats from per-feature moments.
// ---------------------------------------------------------------------------
__global__ void stats_kernel(const float* __restrict__ probe,
                             const float* __restrict__ gallery,
                             const float* __restrict__ gamma,
                             const float* __restrict__ beta)
{
    const int tx = threadIdx.x & 63;
    const int ty = threadIdx.x >> 6;
    const int f  = blockIdx.x * 64 + tx;

    float p1 = 0, p2 = 0, p3 = 0, p4 = 0;
    #pragma unroll 4
    for (int i = ty * 16; i < ty * 16 + 16; i++) {
        float x = probe[i * FEAT + f];
        float x2 = x * x;
        p1 += x; p2 += x2; p3 += x2 * x; p4 += x2 * x2;
    }
    float g1 = 0, g2 = 0, g3 = 0, g4 = 0;
    #pragma unroll 4
    for (int j = ty * 64; j < ty * 64 + 64; j++) {
        float x = gallery[j * FEAT + f];
        float x2 = x * x;
        g1 += x; g2 += x2; g3 += x2 * x; g4 += x2 * x2;
    }

    __shared__ float red[8][4][64];
    red[0][ty][tx] = p1; red[1][ty][tx] = p2;
    red[2][ty][tx] = p3; red[3][ty][tx] = p4;
    red[4][ty][tx] = g1; red[5][ty][tx] = g2;
    red[6][ty][tx] = g3; red[7][ty][tx] = g4;
    __syncthreads();
    if (ty != 0) return;

    p1 = (red[0][0][tx] + red[0][1][tx] + red[0][2][tx] + red[0][3][tx]) * (1.f/NP);
    p2 = (red[1][0][tx] + red[1][1][tx] + red[1][2][tx] + red[1][3][tx]) * (1.f/NP);
    p3 = (red[2][0][tx] + red[2][1][tx] + red[2][2][tx] + red[2][3][tx]) * (1.f/NP);
    p4 = (red[3][0][tx] + red[3][1][tx] + red[3][2][tx] + red[3][3][tx]) * (1.f/NP);
    g1 = (red[4][0][tx] + red[4][1][tx] + red[4][2][tx] + red[4][3][tx]) * (1.f/NG);
    g2 = (red[5][0][tx] + red[5][1][tx] + red[5][2][tx] + red[5][3][tx]) * (1.f/NG);
    g3 = (red[6][0][tx] + red[6][1][tx] + red[6][2][tx] + red[6][3][tx]) * (1.f/NG);
    g4 = (red[7][0][tx] + red[7][1][tx] + red[7][2][tx] + red[7][3][tx]) * (1.f/NG);

    float mean = p2 - 2.f * p1 * g1 + g2;
    float ed2  = p4 - 4.f * p3 * g1 + 6.f * p2 * g2 - 4.f * p1 * g3 + g4;
    float var  = ed2 - mean * mean;
    float s    = gamma[f] * rsqrtf(var + EPSV);
    d_scale[f] = s;
    d_shift[f] = beta[f] - mean * s;
}

// ---------------------------------------------------------------------------
// Stage A2: materialize A = (p-g)^2 as fp16
// ---------------------------------------------------------------------------
__global__ __launch_bounds__(256)
void build_kernel(const float* __restrict__ probe,
                  const float* __restrict__ gallery)
{
    const int n = blockIdx.x;
    const int t = threadIdx.x;
    const int i = n >> 8;
    const int j = n & 255;
    const float4* pp = (const float4*)(probe   + (size_t)i * FEAT) + t * 2;
    const float4* gp = (const float4*)(gallery + (size_t)j * FEAT) + t * 2;
    const float4 pa = pp[0], pb = pp[1], ga = gp[0], gb = gp[1];
    float v0 = pa.x - ga.x; v0 *= v0;
    float v1 = pa.y - ga.y; v1 *= v1;
    float v2 = pa.z - ga.z; v2 *= v2;
    float v3 = pa.w - ga.w; v3 *= v3;
    float v4 = pb.x - gb.x; v4 *= v4;
    float v5 = pb.y - gb.y; v5 *= v5;
    float v6 = pb.z - gb.z; v6 *= v6;
    float v7 = pb.w - gb.w; v7 *= v7;
    d_A16[(size_t)n * 256 + t] = make_uint4(pack16(v0, v1), pack16(v2, v3),
                                            pack16(v4, v5), pack16(v6, v7));
}

// ---------------------------------------------------------------------------
// Stage B: W'[c] = W[c]*scale*512 -> fp16 ; C[c] = b[c] + shift . W[c]
// ---------------------------------------------------------------------------
__global__ void prep_kernel(const float* __restrict__ W,
                            const float* __restrict__ b)
{
    int c = blockIdx.x;
    int t = threadIdx.x;
    if (c >= NCLS) {
        d_Wp16[c * 256 + t] = make_uint4(0, 0, 0, 0);
        if (t == 0) d_C[c] = 0.f;
        return;
    }
    int f0 = t * 8;
    const float4* wp = (const float4*)(W + (size_t)c * FEAT + f0);
    const float4* sp = (const float4*)(d_scale + f0);
    const float4* hp = (const float4*)(d_shift + f0);
    float4 w0 = wp[0], w1 = wp[1];
    float4 s0 = sp[0], s1 = sp[1];
    float4 h0 = hp[0], h1 = hp[1];

    float v0 = w0.x * s0.x * WSCALE, v1 = w0.y * s0.y * WSCALE;
    float v2 = w0.z * s0.z * WSCALE, v3 = w0.w * s0.w * WSCALE;
    float v4 = w1.x * s1.x * WSCALE, v5 = w1.y * s1.y * WSCALE;
    float v6 = w1.z * s1.z * WSCALE, v7 = w1.w * s1.w * WSCALE;
    d_Wp16[c * 256 + t] = make_uint4(pack16(v0, v1), pack16(v2, v3),
                                     pack16(v4, v5), pack16(v6, v7));

    float acc = w0.x*h0.x + w0.y*h0.y + w0.z*h0.z + w0.w*h0.w
              + w1.x*h1.x + w1.y*h1.y + w1.z*h1.z + w1.w*h1.w;
    #pragma unroll
    for (int o = 16; o > 0; o >>= 1)
        acc += __shfl_down_sync(0xFFFFFFFFu, acc, o);
    __shared__ float red[8];
    if ((t & 31) == 0) red[t >> 5] = acc;
    __syncthreads();
    if (t == 0) {
        float s = 0.f;
        #pragma unroll
        for (int w = 0; w < 8; w++) s += red[w];
        d_C[c] = b[c] + s;
    }
}

// ---------------------------------------------------------------------------
// Stage C: pure fp16 mma.sync GEMM; 3-stage cp.async pipeline, wait_group 1.
// ---------------------------------------------------------------------------
__global__ __launch_bounds__(256, 2)
void gemm_kernel(float* __restrict__ out)
{
    extern __shared__ char smem_raw[];
    char* smem = (char*)(((uintptr_t)smem_raw + 1023) & ~(uintptr_t)1023);
    const uint32_t sbase = smem_u32(smem);

    const int tid  = threadIdx.x;
    const int wid  = tid >> 5;
    const int lane = tid & 31;

    const int by    = blockIdx.y;
    const int ibase = (by >> 2) * 2;
    const int jbase = (by & 3) * 64;
    const int cbase = blockIdx.x * TNC;

    // ---- staging mapping: thread -> (tile row r, k-half h) ----
    const int r = tid >> 1;
    const int h = tid & 1;

    const int nrow = (ibase + (r >> 6)) * NG + jbase + (r & 63);
    const uint4* aRow = d_A16  + (size_t)nrow * 256 + h * 4;
    const uint4* wRow = d_Wp16 + (size_t)(cbase + r) * 256 + h * 4;

    const uint32_t cvtOff = (uint32_t)(r * 128 + h * 64);
    uint32_t swz[4];
    #pragma unroll
    for (int q = 0; q < 4; q++) {
        const uint32_t off = cvtOff + q * 16;
        swz[q] = off ^ ((off >> 3) & 0x70u);
    }

    // ---- mma mapping: warp grid 2(m) x 4(n); warp tile 64x32 ----
    const int m0 = (wid >> 2) * 64;
    const int n0 = (wid & 3) * 32;
    const int xr = (lane & 7) * 16;
    const int g  = lane >> 3;                    // ldsm4 lane group 0..3

    uint32_t arow[4], akb[4], brow4[2], bkb4[4];
    #pragma unroll
    for (int mt = 0; mt < 4; mt++)
        arow[mt] = (uint32_t)((m0 + mt * 16 + (lane & 15)) * 128);
    // B ldsm4 p: mats = (nt=2p + (g>>1)) x (k half = g&1)
    #pragma unroll
    for (int p = 0; p < 2; p++)
        brow4[p] = (uint32_t)(16384 +
                   (n0 + (2 * p + (g >> 1)) * 8 + (lane & 7)) * 128);
    #pragma unroll
    for (int kk = 0; kk < 4; kk++) {
        akb[kk]  = (uint32_t)((kk * 32 + (lane >> 4) * 16) ^ xr);
        bkb4[kk] = (uint32_t)((kk * 32 + (g & 1) * 16) ^ xr);
    }

    float acc[4][4][4];
    #pragma unroll
    for (int mt = 0; mt < 4; mt++)
        #pragma unroll
        for (int nt = 0; nt < 4; nt++)
            #pragma unroll
            for (int q = 0; q < 4; q++) acc[mt][nt][q] = 0.f;

    // ---- prologue: stages 0 and 1 ----
    #pragma unroll
    for (int s = 0; s < 2; s++) {
        const uint32_t ad = sbase + s * STAGE_BYTES;
        const uint32_t bd = ad + 16384;
        const uint4* ap = aRow + s * 8;
        const uint4* wp = wRow + s * 8;
        #pragma unroll
        for (int q = 0; q < 4; q++) cp16(ad + swz[q], ap + q);
        #pragma unroll
        for (int q = 0; q < 4; q++) cp16(bd + swz[q], wp + q);
        cp_commit();
    }

    int buf = 0;                      // buffer of stage kt
    int nbuf = 2;                     // buffer for stage kt+2
    for (int kt = 0; kt < KITERS; kt++) {
        cp_wait1();                   // stage kt resident (kt+1 may be in flight)
        __syncthreads();

        if (kt + 2 < KITERS) {
            const uint32_t ad = sbase + nbuf * STAGE_BYTES;
            const uint32_t bd = ad + 16384;
            const uint4* ap = aRow + (kt + 2) * 8;
            const uint4* wp = wRow + (kt + 2) * 8;
            #pragma unroll
            for (int q = 0; q < 4; q++) cp16(ad + swz[q], ap + q);
            #pragma unroll
            for (int q = 0; q < 4; q++) cp16(bd + swz[q], wp + q);
        }
        cp_commit();                  // always commit (empty at tail keeps count)

        const uint32_t sb = sbase + buf * STAGE_BYTES;
        #pragma unroll
        for (int kk = 0; kk < 4; kk++) {
            uint32_t bfa[4], bfb[4];
            ldsm4(bfa, sb + brow4[0] + bkb4[kk]);   // nt 0,1
            ldsm4(bfb, sb + brow4[1] + bkb4[kk]);   // nt 2,3
            #pragma unroll
            for (int mt = 0; mt < 4; mt++) {
                uint32_t ah[4];
                ldsm4(ah, sb + arow[mt] + akb[kk]);
                mma16816(acc[mt][0], ah, &bfa[0]);
                mma16816(acc[mt][1], ah, &bfa[2]);
                mma16816(acc[mt][2], ah, &bfb[0]);
                mma16816(acc[mt][3], ah, &bfb[2]);
            }
        }
        buf  = (buf  == NSTAGE - 1) ? 0 : buf + 1;
        nbuf = (nbuf == NSTAGE - 1) ? 0 : nbuf + 1;
    }

    // ---- epilogue ----
    #pragma unroll
    for (int mt = 0; mt < 4; mt++) {
        const int mlA = m0 + mt * 16 + (lane >> 2);
        const int mlB = mlA + 8;
        const size_t nA = (size_t)((ibase + (mlA >> 6)) * NG + jbase + (mlA & 63));
        const size_t nB = (size_t)((ibase + (mlB >> 6)) * NG + jbase + (mlB & 63));
        #pragma unroll
        for (int nt = 0; nt < 4; nt++) {
            const int c = cbase + n0 + nt * 8 + (lane & 3) * 2;
            const float* a = acc[mt][nt];
            if (c < NCLS) {
                const float Cc = d_C[c];
                out[nA * NCLS + c] = a[0] * OSCALE + Cc;
                out[nB * NCLS + c] = a[2] * OSCALE + Cc;
            }
            if (c + 1 < NCLS) {
                const float Cc = d_C[c + 1];
                out[nA * NCLS + c + 1] = a[1] * OSCALE + Cc;
                out[nB * NCLS + c + 1] = a[3] * OSCALE + Cc;
            }
        }
    }
}

// ---------------------------------------------------------------------------
extern "C" void kernel_launch(void* const* d_in, const int* in_sizes, int n_in,
                              void* d_out, int out_size)
{
    const float* probe   = (const float*)d_in[0];
    const float* gallery = (const float*)d_in[1];
    const float* gamma   = (const float*)d_in[2];
    const float* beta    = (const float*)d_in[3];
    const float* W       = (const float*)d_in[4];
    const float* b       = (const float*)d_in[5];
    float* out = (float*)d_out;

    static bool attr_set = false;
    if (!attr_set) {
        cudaFuncSetAttribute(gemm_kernel,
                             cudaFuncAttributeMaxDynamicSharedMemorySize,
                             SMEM_TOTAL);
        attr_set = true;
    }

    stats_kernel<<<FEAT / 64, 256>>>(probe, gallery, gamma, beta);
    build_kernel<<<NROWS, 256>>>(probe, gallery);
    prep_kernel<<<NCLSP, 256>>>(W, b);
    dim3 grid(NCLSP / TNC, NROWS / TM);   // (6, 128)
    gemm_kernel<<<grid, 256, SMEM_TOTAL>>>(out);
}